// round 6
// baseline (speedup 1.0000x reference)
#include <cuda_runtime.h>
#include <cuda_bf16.h>
#include <cstdint>

// ---------------------------------------------------------------------------
// Problem constants
// ---------------------------------------------------------------------------
#define HIDDEN   1024
#define FRAMES   16
#define SPATIAL  1024
#define BATCH    2
#define NSEQ     (BATCH*SPATIAL)        // 2048
#define TOKENS   (BATCH*FRAMES*SPATIAL) // 32768
#define NH       16
#define HD       64
#define QKV_N    3072
#define KROW     2048                   // int8 row stride: [q1(1024) | q2(1024)]

// ---------------------------------------------------------------------------
// Scratch
// ---------------------------------------------------------------------------
__device__ int8_t g_xq [(size_t)TOKENS * KROW];   // LN'd+transposed quantized
__device__ int8_t g_wqq[(size_t)QKV_N  * KROW];   // w_qkv quantized
__device__ int8_t g_woq[(size_t)HIDDEN * KROW];   // w_out quantized
__device__ int8_t g_aq [(size_t)TOKENS * KROW];   // attn-out quantized
__device__ float  g_qkv [(size_t)TOKENS * QKV_N]; // QKV fp32
__device__ float  g_attn[(size_t)TOKENS * HIDDEN];// attn out fp32 (final order)
__device__ float  g_sx [TOKENS];                  // row scales (= absmax/127)
__device__ float  g_swq[QKV_N];
__device__ float  g_swo[HIDDEN];
__device__ float  g_sa [TOKENS];

// ---------------------------------------------------------------------------
// PTX helpers (sm_80-era, compile at base sm_103)
// ---------------------------------------------------------------------------
__device__ __forceinline__ uint32_t smem_u32(const void* p) {
    uint32_t a;
    asm("{ .reg .u64 t; cvta.to.shared.u64 t, %1; cvt.u32.u64 %0, t; }" : "=r"(a) : "l"(p));
    return a;
}
__device__ __forceinline__ void cp16(uint32_t dst, const void* src) {
    asm volatile("cp.async.cg.shared.global [%0], [%1], 16;" :: "r"(dst), "l"(src));
}
#define CP_COMMIT() asm volatile("cp.async.commit_group;" ::: "memory")
#define CP_WAIT2()  asm volatile("cp.async.wait_group 2;" ::: "memory")

__device__ __forceinline__ void ldmx4(uint32_t addr, uint32_t* r) {
    asm volatile("ldmatrix.sync.aligned.m8n8.x4.shared.b16 {%0,%1,%2,%3}, [%4];"
        : "=r"(r[0]), "=r"(r[1]), "=r"(r[2]), "=r"(r[3]) : "r"(addr));
}
__device__ __forceinline__ void mma_s8(int* d, const uint32_t* a, uint32_t b0, uint32_t b1) {
    asm volatile("mma.sync.aligned.m16n8k32.row.col.s32.s8.s8.s32 "
        "{%0,%1,%2,%3},{%4,%5,%6,%7},{%8,%9},{%0,%1,%2,%3};"
        : "+r"(d[0]), "+r"(d[1]), "+r"(d[2]), "+r"(d[3])
        : "r"(a[0]), "r"(a[1]), "r"(a[2]), "r"(a[3]), "r"(b0), "r"(b1));
}

// byte offset of 16B chunk (r, ch) in a [rows x 64B] tile, XOR-swizzled
__device__ __forceinline__ uint32_t toff(int r, int ch) {
    return (uint32_t)(r * 64 + ((ch ^ ((r >> 1) & 3)) << 4));
}

// two-level int8 quantize of x given inv = 127/absmax
__device__ __forceinline__ void q2lvl(float x, float inv, int8_t& q1, int8_t& q2) {
    const float t  = x * inv;
    const float f1 = rintf(t);
    const float f2 = rintf((t - f1) * 128.0f);
    q1 = (int8_t)(int)f1;
    q2 = (int8_t)(int)f2;
}

// ---------------------------------------------------------------------------
// Kernel 1: LayerNorm + temporal transpose -> two-level int8 + row scale
// ---------------------------------------------------------------------------
__global__ __launch_bounds__(256) void ln_transpose_kernel(
    const float* __restrict__ x,
    const float* __restrict__ gamma,
    const float* __restrict__ beta)
{
    const int token = blockIdx.x;
    const int b  = token >> 14;
    const int sg = token & 16383;
    const int t  = sg >> 10;
    const int s  = sg & 1023;

    const int tid = threadIdx.x;
    const float4 v = ((const float4*)(x + (size_t)token * HIDDEN))[tid];

    float sum = v.x + v.y + v.z + v.w;
    float sq  = v.x*v.x + v.y*v.y + v.z*v.z + v.w*v.w;

    #pragma unroll
    for (int o = 16; o > 0; o >>= 1) {
        sum += __shfl_xor_sync(0xffffffffu, sum, o);
        sq  += __shfl_xor_sync(0xffffffffu, sq,  o);
    }
    __shared__ float s_sum[8], s_sq[8], s_mx[8];
    __shared__ float s_mu, s_rstd, s_scale;
    if ((tid & 31) == 0) { s_sum[tid >> 5] = sum; s_sq[tid >> 5] = sq; }
    __syncthreads();
    if (tid == 0) {
        float ts = 0.f, tq = 0.f;
        #pragma unroll
        for (int i = 0; i < 8; ++i) { ts += s_sum[i]; tq += s_sq[i]; }
        const float mu  = ts * (1.0f / HIDDEN);
        const float var = tq * (1.0f / HIDDEN) - mu * mu;
        s_mu = mu;
        s_rstd = rsqrtf(var + 1e-5f);
    }
    __syncthreads();
    const float mu = s_mu, rs = s_rstd;

    const float4 g  = ((const float4*)gamma)[tid];
    const float4 be = ((const float4*)beta)[tid];
    float o[4];
    o[0] = (v.x - mu) * rs * g.x + be.x;
    o[1] = (v.y - mu) * rs * g.y + be.y;
    o[2] = (v.z - mu) * rs * g.z + be.z;
    o[3] = (v.w - mu) * rs * g.w + be.w;

    // row absmax
    float mx = fmaxf(fmaxf(fabsf(o[0]), fabsf(o[1])), fmaxf(fabsf(o[2]), fabsf(o[3])));
    #pragma unroll
    for (int of = 16; of > 0; of >>= 1) mx = fmaxf(mx, __shfl_xor_sync(0xffffffffu, mx, of));
    if ((tid & 31) == 0) s_mx[tid >> 5] = mx;
    __syncthreads();
    const size_t orow = (size_t)(b * SPATIAL + s) * FRAMES + t;
    if (tid == 0) {
        float m = 0.f;
        #pragma unroll
        for (int i = 0; i < 8; ++i) m = fmaxf(m, s_mx[i]);
        s_scale = (m > 0.f) ? (127.0f / m) : 0.f;
        g_sx[orow] = (m > 0.f) ? (m * (1.0f / 127.0f)) : 0.f;
    }
    __syncthreads();
    const float inv = s_scale;

    int8_t q1[4], q2[4];
    #pragma unroll
    for (int i = 0; i < 4; ++i) q2lvl(o[i], inv, q1[i], q2[i]);

    int8_t* dst = g_xq + orow * KROW + 4 * tid;
    *(uint32_t*)(dst)        = *(uint32_t*)q1;
    *(uint32_t*)(dst + 1024) = *(uint32_t*)q2;
}

// ---------------------------------------------------------------------------
// Row quantizer: fp32 [rows x 1024] -> int8 [q1|q2] + scale
// ---------------------------------------------------------------------------
__global__ __launch_bounds__(256) void rowquant_kernel(
    const float* __restrict__ src, int8_t* __restrict__ q, float* __restrict__ scale)
{
    const int row = blockIdx.x;
    const int tid = threadIdx.x;
    const float4 v = ((const float4*)(src + (size_t)row * 1024))[tid];

    float mx = fmaxf(fmaxf(fabsf(v.x), fabsf(v.y)), fmaxf(fabsf(v.z), fabsf(v.w)));
    #pragma unroll
    for (int o = 16; o > 0; o >>= 1) mx = fmaxf(mx, __shfl_xor_sync(0xffffffffu, mx, o));
    __shared__ float s_mx[8];
    __shared__ float s_inv;
    if ((tid & 31) == 0) s_mx[tid >> 5] = mx;
    __syncthreads();
    if (tid == 0) {
        float m = 0.f;
        #pragma unroll
        for (int i = 0; i < 8; ++i) m = fmaxf(m, s_mx[i]);
        s_inv = (m > 0.f) ? (127.0f / m) : 0.f;
        scale[row] = (m > 0.f) ? (m * (1.0f / 127.0f)) : 0.f;
    }
    __syncthreads();
    const float inv = s_inv;

    const float o[4] = {v.x, v.y, v.z, v.w};
    int8_t q1[4], q2[4];
    #pragma unroll
    for (int i = 0; i < 4; ++i) q2lvl(o[i], inv, q1[i], q2[i]);
    int8_t* dst = q + (size_t)row * KROW + 4 * tid;
    *(uint32_t*)(dst)        = *(uint32_t*)q1;
    *(uint32_t*)(dst + 1024) = *(uint32_t*)q2;
}

// ---------------------------------------------------------------------------
// Two-level int8 GEMM: C[M,N] = dequant( A ~ [q1|q2], B ~ [p1|p2] )
//   acc1 = q1*p1 (K); acc2 = q1*p2 + q2*p1 (2K); C = sA*sB*(acc1 + acc2/128)
// BM=BN=128, BK=64 int8; 512 threads (16 warps, 2x8 of 64x16); 4-stage cp.async.
// ---------------------------------------------------------------------------
#define NCHUNK 48                 // 3 * (1024/64)
#define STG_B  16384              // A 8KB + B 8KB per stage

__global__ __launch_bounds__(512, 1) void gemm_s8(
    const int8_t* __restrict__ A,
    const int8_t* __restrict__ B,
    const float*  __restrict__ sA,
    const float*  __restrict__ sB,
    float* __restrict__ C, int N)
{
    extern __shared__ int8_t smem[];
    const uint32_t base = smem_u32(smem);

    const int tid  = threadIdx.x;
    const int lane = tid & 31;
    const int wid  = tid >> 5;
    const int wm   = wid >> 3;         // 0..1
    const int wn   = wid & 7;          // 0..7
    const int bm   = blockIdx.y * 128;
    const int bn   = blockIdx.x * 128;

    // staging: 1 A-chunk + 1 B-chunk per thread per stage
    const int sr  = tid >> 2;          // 0..127
    const int sch = tid & 3;
    const int8_t* aSrc = A + (size_t)(bm + sr) * KROW + sch * 16;
    const int8_t* bSrc = B + (size_t)(bn + sr) * KROW + sch * 16;
    const uint32_t aDst = base + toff(sr, sch);
    const uint32_t bDst = aDst + 8192;

    // chunk c -> segment offsets: A: q1,q1,q2 ; B: p1,p2,p1
    #define OFFA(c) ((((c) >= 32) ? 1024 : 0) + (((c) & 15) << 6))
    #define OFFB(c) (((((c) >= 16) && ((c) < 32)) ? 1024 : 0) + (((c) & 15) << 6))
    #define LOAD(c)                                              \
    {                                                            \
        const uint32_t so = ((c) & 3) * STG_B;                   \
        cp16(aDst + so, aSrc + OFFA(c));                         \
        cp16(bDst + so, bSrc + OFFB(c));                         \
    }

    // fragment smem offsets within a stage
    uint32_t a_off[4][2], b_off[2];
    #pragma unroll
    for (int mi = 0; mi < 4; ++mi)
        #pragma unroll
        for (int kk = 0; kk < 2; ++kk) {
            const int r  = wm * 64 + mi * 16 + (lane & 7) + ((lane >> 3) & 1) * 8;
            const int ch = kk * 2 + (lane >> 4);
            a_off[mi][kk] = toff(r, ch);
        }
    #pragma unroll
    for (int kk = 0; kk < 2; ++kk) {
        const int r  = wn * 16 + (lane & 7) + ((lane >> 3) & 1) * 8;
        const int ch = kk * 2 + (lane >> 4);
        b_off[kk] = toff(r, ch) + 8192;
    }

    int acc1[4][2][4], acc2[4][2][4];
    #pragma unroll
    for (int i = 0; i < 4; ++i)
        #pragma unroll
        for (int j = 0; j < 2; ++j)
            #pragma unroll
            for (int e = 0; e < 4; ++e) { acc1[i][j][e] = 0; acc2[i][j][e] = 0; }

    LOAD(0); CP_COMMIT();
    LOAD(1); CP_COMMIT();
    LOAD(2); CP_COMMIT();

    #define COMPUTE(ACC, so)                                     \
    {                                                            \
        _Pragma("unroll")                                        \
        for (int kk = 0; kk < 2; ++kk) {                         \
            uint32_t bq[4];                                      \
            ldmx4((so) + b_off[kk], bq);                         \
            _Pragma("unroll")                                    \
            for (int mi = 0; mi < 4; ++mi) {                     \
                uint32_t aq[4];                                  \
                ldmx4((so) + a_off[mi][kk], aq);                 \
                mma_s8(ACC[mi][0], aq, bq[0], bq[2]);            \
                mma_s8(ACC[mi][1], aq, bq[1], bq[3]);            \
            }                                                    \
        }                                                        \
    }

    #pragma unroll 1
    for (int c = 0; c < NCHUNK; ++c) {
        CP_WAIT2();
        __syncthreads();
        const uint32_t so = base + (c & 3) * STG_B;
        if (c < 16) COMPUTE(acc1, so) else COMPUTE(acc2, so);
        if (c + 3 < NCHUNK) LOAD(c + 3);
        CP_COMMIT();
    }
    #undef COMPUTE
    #undef LOAD

    // epilogue: dequant + store
    #pragma unroll
    for (int mi = 0; mi < 4; ++mi) {
        const int row = bm + wm * 64 + mi * 16 + (lane >> 2);
        const float sa0 = sA[row], sa1 = sA[row + 8];
        #pragma unroll
        for (int nj = 0; nj < 2; ++nj) {
            const int col = bn + wn * 16 + nj * 8 + (lane & 3) * 2;
            const float sb0 = sB[col], sb1 = sB[col + 1];
            const float v00 = sa0 * sb0 * ((float)acc1[mi][nj][0] + (float)acc2[mi][nj][0] * 0.0078125f);
            const float v01 = sa0 * sb1 * ((float)acc1[mi][nj][1] + (float)acc2[mi][nj][1] * 0.0078125f);
            const float v10 = sa1 * sb0 * ((float)acc1[mi][nj][2] + (float)acc2[mi][nj][2] * 0.0078125f);
            const float v11 = sa1 * sb1 * ((float)acc1[mi][nj][3] + (float)acc2[mi][nj][3] * 0.0078125f);
            *(float2*)(C + (size_t)row * N + col)       = make_float2(v00, v01);
            *(float2*)(C + (size_t)(row + 8) * N + col) = make_float2(v10, v11);
        }
    }
}

// ---------------------------------------------------------------------------
// Kernel 3: RoPE + causal attention; fp32 out in final token order
// ---------------------------------------------------------------------------
__global__ __launch_bounds__(64) void attn_kernel()
{
    const int nb = blockIdx.x;
    const int n  = nb >> 4;
    const int hh = nb & 15;
    const int tid = threadIdx.x;

    __shared__ float qs[FRAMES][HD + 1];
    __shared__ float ks[FRAMES][HD + 1];
    __shared__ float vs[FRAMES][HD + 1];
    __shared__ float P [FRAMES][FRAMES + 1];

    const float* bptr = g_qkv + (size_t)n * FRAMES * QKV_N;

    for (int idx = tid; idx < FRAMES * HD; idx += 64) {
        const int t = idx >> 6;
        const int d = idx & 63;
        const size_t r = (size_t)t * QKV_N + hh * HD + d;
        qs[t][d] = bptr[r];
        ks[t][d] = bptr[r + HIDDEN];
        vs[t][d] = bptr[r + 2 * HIDDEN];
    }
    __syncthreads();

    for (int idx = tid; idx < FRAMES * 32; idx += 64) {
        const int t = idx >> 5;
        const int d = idx & 31;
        const float inv = __expf(-(float)d * 0.28782313662425576f);
        float sn, cs;
        __sincosf((float)t * inv, &sn, &cs);
        const float q1 = qs[t][d], q2 = qs[t][d + 32];
        qs[t][d]      = q1 * cs - q2 * sn;
        qs[t][d + 32] = q2 * cs + q1 * sn;
        const float k1 = ks[t][d], k2 = ks[t][d + 32];
        ks[t][d]      = k1 * cs - k2 * sn;
        ks[t][d + 32] = k2 * cs + k1 * sn;
    }
    __syncthreads();

    for (int idx = tid; idx < FRAMES * FRAMES; idx += 64) {
        const int i = idx >> 4;
        const int j = idx & 15;
        float v = -INFINITY;
        if (j <= i) {
            float acc = 0.f;
            #pragma unroll
            for (int d = 0; d < HD; ++d) acc += qs[i][d] * ks[j][d];
            v = acc * 0.125f;
        }
        P[i][j] = v;
    }
    __syncthreads();

    if (tid < FRAMES) {
        const int i = tid;
        float m = -INFINITY;
        for (int j = 0; j <= i; ++j) m = fmaxf(m, P[i][j]);
        float sum = 0.f;
        for (int j = 0; j <= i; ++j) { const float e = expf(P[i][j] - m); P[i][j] = e; sum += e; }
        const float r = 1.f / sum;
        for (int j = 0; j <= i; ++j) P[i][j] *= r;
        for (int j = i + 1; j < FRAMES; ++j) P[i][j] = 0.f;
    }
    __syncthreads();

    const int d = tid;
    const int b = n >> 10;
    const int s = n & 1023;
    #pragma unroll
    for (int i = 0; i < FRAMES; ++i) {
        float acc = 0.f;
        #pragma unroll
        for (int j = 0; j < FRAMES; ++j) acc += P[i][j] * vs[j][d];
        g_attn[(size_t)(b * 16384 + i * 1024 + s) * HIDDEN + hh * HD + d] = acc;
    }
}

// ---------------------------------------------------------------------------
// Launch
// ---------------------------------------------------------------------------
extern "C" void kernel_launch(void* const* d_in, const int* in_sizes, int n_in,
                              void* d_out, int out_size)
{
    const float* x      = (const float*)d_in[0];
    const float* w_qkv  = (const float*)d_in[1];
    const float* w_out  = (const float*)d_in[2];
    const float* gamma  = (const float*)d_in[3];
    const float* beta   = (const float*)d_in[4];
    float* out = (float*)d_out;

    int8_t *xq, *wqq, *woq, *aq;
    float *qkv, *attn, *sx, *swq, *swo, *sa;
    cudaGetSymbolAddress((void**)&xq,  g_xq);
    cudaGetSymbolAddress((void**)&wqq, g_wqq);
    cudaGetSymbolAddress((void**)&woq, g_woq);
    cudaGetSymbolAddress((void**)&aq,  g_aq);
    cudaGetSymbolAddress((void**)&qkv, g_qkv);
    cudaGetSymbolAddress((void**)&attn, g_attn);
    cudaGetSymbolAddress((void**)&sx,  g_sx);
    cudaGetSymbolAddress((void**)&swq, g_swq);
    cudaGetSymbolAddress((void**)&swo, g_swo);
    cudaGetSymbolAddress((void**)&sa,  g_sa);

    cudaFuncSetAttribute(gemm_s8, cudaFuncAttributeMaxDynamicSharedMemorySize, 4 * STG_B);

    // 1. LN + temporal transpose -> int8 two-level
    ln_transpose_kernel<<<TOKENS, 256>>>(x, gamma, beta);

    // 1b. weight quantization
    rowquant_kernel<<<QKV_N, 256>>>(w_qkv, wqq, swq);
    rowquant_kernel<<<HIDDEN, 256>>>(w_out, woq, swo);

    // 2. QKV projection: int8x2 GEMM -> fp32
    {
        dim3 grid(QKV_N / 128, TOKENS / 128);
        gemm_s8<<<grid, 512, 4 * STG_B>>>(xq, wqq, sx, swq, qkv, QKV_N);
    }

    // 3. RoPE + causal attention -> fp32 final order
    attn_kernel<<<NSEQ * NH, 64>>>();

    // 3b. quantize attention output rows
    rowquant_kernel<<<TOKENS, 256>>>(attn, aq, sa);

    // 4. Output projection -> d_out fp32
    {
        dim3 grid(HIDDEN / 128, TOKENS / 128);
        gemm_s8<<<grid, 512, 4 * STG_B>>>(aq, woq, sa, swo, out, HIDDEN);
    }
}

// round 7
// speedup vs baseline: 5.6874x; 5.6874x over previous
#include <cuda_runtime.h>
#include <cuda_fp16.h>
#include <cstdint>

// ---------------------------------------------------------------------------
// Problem constants
// ---------------------------------------------------------------------------
#define HIDDEN   1024
#define FRAMES   16
#define SPATIAL  1024
#define BATCH    2
#define NSEQ     (BATCH*SPATIAL)        // 2048
#define TOKENS   (BATCH*FRAMES*SPATIAL) // 32768
#define NH       16
#define HD       64
#define QKV_N    3072

// ---------------------------------------------------------------------------
// Scratch
// ---------------------------------------------------------------------------
__device__ __half g_xh [(size_t)TOKENS * HIDDEN];  // LN'd + transposed, fp16
__device__ __half g_wqh[(size_t)QKV_N  * HIDDEN];  // w_qkv fp16
__device__ __half g_woh[(size_t)HIDDEN * HIDDEN];  // w_out fp16
__device__ __half g_ah [(size_t)TOKENS * HIDDEN];  // attn out fp16, final order
__device__ float  g_qkv[(size_t)TOKENS * QKV_N];   // QKV fp32

// ---------------------------------------------------------------------------
// PTX helpers (sm_80-era, compile at base sm_103)
// ---------------------------------------------------------------------------
__device__ __forceinline__ uint32_t smem_u32(const void* p) {
    uint32_t a;
    asm("{ .reg .u64 t; cvta.to.shared.u64 t, %1; cvt.u32.u64 %0, t; }" : "=r"(a) : "l"(p));
    return a;
}
__device__ __forceinline__ void cp16(uint32_t dst, const void* src) {
    asm volatile("cp.async.cg.shared.global [%0], [%1], 16;" :: "r"(dst), "l"(src));
}
#define CP_COMMIT() asm volatile("cp.async.commit_group;" ::: "memory")
#define CP_WAIT2()  asm volatile("cp.async.wait_group 2;" ::: "memory")

__device__ __forceinline__ void ldmx4(uint32_t addr, uint32_t* r) {
    asm volatile("ldmatrix.sync.aligned.m8n8.x4.shared.b16 {%0,%1,%2,%3}, [%4];"
        : "=r"(r[0]), "=r"(r[1]), "=r"(r[2]), "=r"(r[3]) : "r"(addr));
}
__device__ __forceinline__ void mma_f16(float* d, const uint32_t* a, const uint32_t* b) {
    asm volatile("mma.sync.aligned.m16n8k16.row.col.f32.f16.f16.f32 "
        "{%0,%1,%2,%3},{%4,%5,%6,%7},{%8,%9},{%0,%1,%2,%3};"
        : "+f"(d[0]), "+f"(d[1]), "+f"(d[2]), "+f"(d[3])
        : "r"(a[0]), "r"(a[1]), "r"(a[2]), "r"(a[3]), "r"(b[0]), "r"(b[1]));
}

// byte offset of 16B chunk (r, ch) in a [rows x 64B] tile, XOR-swizzled
__device__ __forceinline__ uint32_t toff(int r, int ch) {
    return (uint32_t)(r * 64 + ((ch ^ ((r >> 1) & 3)) << 4));
}

// ---------------------------------------------------------------------------
// Kernel 1: LayerNorm + temporal transpose -> fp16
// ---------------------------------------------------------------------------
__global__ __launch_bounds__(256) void ln_transpose_kernel(
    const float* __restrict__ x,
    const float* __restrict__ gamma,
    const float* __restrict__ beta)
{
    const int token = blockIdx.x;
    const int b  = token >> 14;
    const int sg = token & 16383;
    const int t  = sg >> 10;
    const int s  = sg & 1023;

    const int tid = threadIdx.x;
    const float4 v = ((const float4*)(x + (size_t)token * HIDDEN))[tid];

    float sum = v.x + v.y + v.z + v.w;
    float sq  = v.x*v.x + v.y*v.y + v.z*v.z + v.w*v.w;

    #pragma unroll
    for (int o = 16; o > 0; o >>= 1) {
        sum += __shfl_xor_sync(0xffffffffu, sum, o);
        sq  += __shfl_xor_sync(0xffffffffu, sq,  o);
    }
    __shared__ float s_sum[8], s_sq[8];
    __shared__ float s_mu, s_rstd;
    if ((tid & 31) == 0) { s_sum[tid >> 5] = sum; s_sq[tid >> 5] = sq; }
    __syncthreads();
    if (tid == 0) {
        float ts = 0.f, tq = 0.f;
        #pragma unroll
        for (int i = 0; i < 8; ++i) { ts += s_sum[i]; tq += s_sq[i]; }
        const float mu  = ts * (1.0f / HIDDEN);
        const float var = tq * (1.0f / HIDDEN) - mu * mu;
        s_mu = mu;
        s_rstd = rsqrtf(var + 1e-5f);
    }
    __syncthreads();
    const float mu = s_mu, rs = s_rstd;

    const float4 g  = ((const float4*)gamma)[tid];
    const float4 be = ((const float4*)beta)[tid];
    __half h[4];
    h[0] = __float2half_rn((v.x - mu) * rs * g.x + be.x);
    h[1] = __float2half_rn((v.y - mu) * rs * g.y + be.y);
    h[2] = __float2half_rn((v.z - mu) * rs * g.z + be.z);
    h[3] = __float2half_rn((v.w - mu) * rs * g.w + be.w);

    const size_t orow = (size_t)(b * SPATIAL + s) * FRAMES + t;
    *(uint2*)(g_xh + orow * HIDDEN + 4 * tid) = *(uint2*)h;
}

// ---------------------------------------------------------------------------
// fp32 -> fp16 weight convert
// ---------------------------------------------------------------------------
__global__ __launch_bounds__(256) void w2h_kernel(
    const float* __restrict__ w, __half* __restrict__ wh, int total)
{
    const int idx = (blockIdx.x * 256 + threadIdx.x) * 4;
    if (idx >= total) return;
    const float4 v = *(const float4*)(w + idx);
    __half h[4] = { __float2half_rn(v.x), __float2half_rn(v.y),
                    __float2half_rn(v.z), __float2half_rn(v.w) };
    *(uint2*)(wh + idx) = *(uint2*)h;
}

// ---------------------------------------------------------------------------
// fp16 mma.sync GEMM: C[M,N] = A[M,1024] * B[N,1024]^T  (fp16 in, fp32 out)
// BM=128, BN=256, BK=32; 512 threads (16 warps 2x8, warp tile 64x32);
// 4-stage cp.async ring, ONE __syncthreads per chunk.
// ---------------------------------------------------------------------------
#define KCH 32                    // 1024 / 32
#define A_STG 8192                // 128*32*2
#define B_STG 16384               // 256*32*2
#define STG   (A_STG + B_STG)     // 24576
#define GEMM_SMEM (4 * STG)       // 98304

__global__ __launch_bounds__(512, 1) void gemm_f16(
    const __half* __restrict__ A,
    const __half* __restrict__ B,
    float* __restrict__ C, int N)
{
    extern __shared__ __half smem[];
    const uint32_t base = smem_u32(smem);

    const int tid  = threadIdx.x;
    const int lane = tid & 31;
    const int wid  = tid >> 5;
    const int wm   = wid >> 3;         // 0..1
    const int wn   = wid & 7;          // 0..7
    const int bm   = blockIdx.y * 128;
    const int bn   = blockIdx.x * 256;

    // staging: A 512x16B (1/thread), B 1024x16B (2/thread)
    const int sr = tid >> 2;           // 0..127
    const int sc = tid & 3;
    const char* aSrc  = (const char*)(A + (size_t)(bm + sr) * HIDDEN) + sc * 16;
    const char* bSrc0 = (const char*)(B + (size_t)(bn + sr) * HIDDEN) + sc * 16;
    const char* bSrc1 = (const char*)(B + (size_t)(bn + sr + 128) * HIDDEN) + sc * 16;
    const uint32_t aDst  = base + toff(sr, sc);
    const uint32_t bDst0 = base + A_STG + toff(sr, sc);
    const uint32_t bDst1 = base + A_STG + toff(sr + 128, sc);

    #define LOAD(c)                                              \
    {                                                            \
        const uint32_t so = ((c) & 3) * STG;                     \
        const int koff = (c) * 64;                               \
        cp16(aDst  + so, aSrc  + koff);                          \
        cp16(bDst0 + so, bSrc0 + koff);                          \
        cp16(bDst1 + so, bSrc1 + koff);                          \
    }

    // fragment smem offsets within a stage
    uint32_t a_off[4][2], b_off[2][2];
    #pragma unroll
    for (int mi = 0; mi < 4; ++mi)
        #pragma unroll
        for (int kk = 0; kk < 2; ++kk) {
            const int r  = wm * 64 + mi * 16 + (lane & 7) + ((lane >> 3) & 1) * 8;
            const int ch = kk * 2 + (lane >> 4);
            a_off[mi][kk] = toff(r, ch);
        }
    #pragma unroll
    for (int p = 0; p < 2; ++p)
        #pragma unroll
        for (int kk = 0; kk < 2; ++kk) {
            const int r  = wn * 32 + p * 16 + (lane & 7) + (lane >> 4) * 8;
            const int ch = kk * 2 + ((lane >> 3) & 1);
            b_off[p][kk] = A_STG + toff(r, ch);
        }

    float acc[4][4][4];
    #pragma unroll
    for (int i = 0; i < 4; ++i)
        #pragma unroll
        for (int j = 0; j < 4; ++j)
            #pragma unroll
            for (int e = 0; e < 4; ++e) acc[i][j][e] = 0.f;

    LOAD(0); CP_COMMIT();
    LOAD(1); CP_COMMIT();
    LOAD(2); CP_COMMIT();

    #pragma unroll 1
    for (int c = 0; c < KCH; ++c) {
        CP_WAIT2();
        __syncthreads();

        const uint32_t so = base + (c & 3) * STG;

        #pragma unroll
        for (int kk = 0; kk < 2; ++kk) {
            uint32_t bq[2][4];
            ldmx4(so + b_off[0][kk], bq[0]);
            ldmx4(so + b_off[1][kk], bq[1]);
            #pragma unroll
            for (int mi = 0; mi < 4; ++mi) {
                uint32_t aq[4];
                ldmx4(so + a_off[mi][kk], aq);
                #pragma unroll
                for (int nj = 0; nj < 4; ++nj)
                    mma_f16(acc[mi][nj], aq, &bq[nj >> 1][(nj & 1) * 2]);
            }
        }

        if (c + 3 < KCH) LOAD(c + 3);
        CP_COMMIT();
    }
    #undef LOAD

    // epilogue
    #pragma unroll
    for (int mi = 0; mi < 4; ++mi) {
        const int row = bm + wm * 64 + mi * 16 + (lane >> 2);
        #pragma unroll
        for (int nj = 0; nj < 4; ++nj) {
            const int col = bn + wn * 32 + nj * 8 + (lane & 3) * 2;
            *(float2*)(C + (size_t)row * N + col)       = make_float2(acc[mi][nj][0], acc[mi][nj][1]);
            *(float2*)(C + (size_t)(row + 8) * N + col) = make_float2(acc[mi][nj][2], acc[mi][nj][3]);
        }
    }
}

// ---------------------------------------------------------------------------
// Kernel 3: RoPE + causal attention; writes fp16 in final token order
// ---------------------------------------------------------------------------
__global__ __launch_bounds__(64) void attn_kernel()
{
    const int nb = blockIdx.x;
    const int n  = nb >> 4;
    const int hh = nb & 15;
    const int tid = threadIdx.x;

    __shared__ float qs[FRAMES][HD + 1];
    __shared__ float ks[FRAMES][HD + 1];
    __shared__ float vs[FRAMES][HD + 1];
    __shared__ float P [FRAMES][FRAMES + 1];

    const float* bptr = g_qkv + (size_t)n * FRAMES * QKV_N;

    for (int idx = tid; idx < FRAMES * HD; idx += 64) {
        const int t = idx >> 6;
        const int d = idx & 63;
        const size_t r = (size_t)t * QKV_N + hh * HD + d;
        qs[t][d] = bptr[r];
        ks[t][d] = bptr[r + HIDDEN];
        vs[t][d] = bptr[r + 2 * HIDDEN];
    }
    __syncthreads();

    for (int idx = tid; idx < FRAMES * 32; idx += 64) {
        const int t = idx >> 5;
        const int d = idx & 31;
        const float inv = __expf(-(float)d * 0.28782313662425576f);
        float sn, cs;
        __sincosf((float)t * inv, &sn, &cs);
        const float q1 = qs[t][d], q2 = qs[t][d + 32];
        qs[t][d]      = q1 * cs - q2 * sn;
        qs[t][d + 32] = q2 * cs + q1 * sn;
        const float k1 = ks[t][d], k2 = ks[t][d + 32];
        ks[t][d]      = k1 * cs - k2 * sn;
        ks[t][d + 32] = k2 * cs + k1 * sn;
    }
    __syncthreads();

    for (int idx = tid; idx < FRAMES * FRAMES; idx += 64) {
        const int i = idx >> 4;
        const int j = idx & 15;
        float v = -INFINITY;
        if (j <= i) {
            float acc = 0.f;
            #pragma unroll
            for (int d = 0; d < HD; ++d) acc += qs[i][d] * ks[j][d];
            v = acc * 0.125f;
        }
        P[i][j] = v;
    }
    __syncthreads();

    if (tid < FRAMES) {
        const int i = tid;
        float m = -INFINITY;
        for (int j = 0; j <= i; ++j) m = fmaxf(m, P[i][j]);
        float sum = 0.f;
        for (int j = 0; j <= i; ++j) { const float e = expf(P[i][j] - m); P[i][j] = e; sum += e; }
        const float r = 1.f / sum;
        for (int j = 0; j <= i; ++j) P[i][j] *= r;
        for (int j = i + 1; j < FRAMES; ++j) P[i][j] = 0.f;
    }
    __syncthreads();

    const int d = tid;
    const int b = n >> 10;
    const int s = n & 1023;
    #pragma unroll
    for (int i = 0; i < FRAMES; ++i) {
        float acc = 0.f;
        #pragma unroll
        for (int j = 0; j < FRAMES; ++j) acc += P[i][j] * vs[j][d];
        g_ah[(size_t)(b * 16384 + i * 1024 + s) * HIDDEN + hh * HD + d] = __float2half_rn(acc);
    }
}

// ---------------------------------------------------------------------------
// Launch
// ---------------------------------------------------------------------------
extern "C" void kernel_launch(void* const* d_in, const int* in_sizes, int n_in,
                              void* d_out, int out_size)
{
    const float* x      = (const float*)d_in[0];
    const float* w_qkv  = (const float*)d_in[1];
    const float* w_out  = (const float*)d_in[2];
    const float* gamma  = (const float*)d_in[3];
    const float* beta   = (const float*)d_in[4];
    float* out = (float*)d_out;

    __half *xh, *wqh, *woh, *ah;
    float *qkv;
    cudaGetSymbolAddress((void**)&xh,  g_xh);
    cudaGetSymbolAddress((void**)&wqh, g_wqh);
    cudaGetSymbolAddress((void**)&woh, g_woh);
    cudaGetSymbolAddress((void**)&ah,  g_ah);
    cudaGetSymbolAddress((void**)&qkv, g_qkv);

    cudaFuncSetAttribute(gemm_f16, cudaFuncAttributeMaxDynamicSharedMemorySize, GEMM_SMEM);

    // 1. LN + temporal transpose -> fp16
    ln_transpose_kernel<<<TOKENS, 256>>>(x, gamma, beta);

    // 1b. weight conversion
    w2h_kernel<<<(QKV_N * 1024 / 4 + 255) / 256, 256>>>(w_qkv, wqh, QKV_N * 1024);
    w2h_kernel<<<(HIDDEN * 1024 / 4 + 255) / 256, 256>>>(w_out, woh, HIDDEN * 1024);

    // 2. QKV projection: fp16 GEMM -> fp32
    {
        dim3 grid(QKV_N / 256, TOKENS / 128);
        gemm_f16<<<grid, 512, GEMM_SMEM>>>(xh, wqh, qkv, QKV_N);
    }

    // 3. RoPE + causal attention -> fp16 final order
    attn_kernel<<<NSEQ * NH, 64>>>();

    // 4. Output projection -> d_out fp32
    {
        dim3 grid(HIDDEN / 256, TOKENS / 128);
        gemm_f16<<<grid, 512, GEMM_SMEM>>>(ah, woh, out, HIDDEN);
    }
}